// round 1
// baseline (speedup 1.0000x reference)
#include <cuda_runtime.h>
#include <math.h>

// Problem constants
#define BB 2
#define SS 2048
#define DM 1024
#define NH 16
#define HD 64
#define MROWS (BB*SS)        // 4096

// Scratch (device globals; no allocations allowed)
__device__ float g_Q[BB*NH*SS*HD];     // [b,h,s,d]
__device__ float g_K[BB*NH*SS*HD];
__device__ float g_V[BB*NH*SS*HD];
__device__ float g_att[BB*SS*DM];      // [b,s, h*64+d]

// ---------------------------------------------------------------------------
// Tiled SGEMM: C[M,N] = A[M,K] @ B[K,N] + bias[N]
// BM=BN=128, BK=8, 256 threads, 8x8 per thread.
// head_split: write C in [b,h,s,d] layout instead of row-major.
// ---------------------------------------------------------------------------
__global__ __launch_bounds__(256) void gemm128(
    const float* __restrict__ A, const float* __restrict__ B,
    const float* __restrict__ bias, float* __restrict__ C,
    int M, int N, int K, int head_split)
{
    __shared__ float As[8][128];   // As[k][m]
    __shared__ float Bs[8][128];   // Bs[k][n]

    const int tid  = threadIdx.x;
    const int row0 = blockIdx.y * 128;
    const int col0 = blockIdx.x * 128;
    const int ty   = tid >> 4;     // 0..15
    const int tx   = tid & 15;     // 0..15

    // global load mapping
    const int ar = tid >> 1;           // 0..127
    const int ak = (tid & 1) * 4;      // 0 or 4
    const int br = tid >> 5;           // 0..7
    const int bc = (tid & 31) * 4;     // 0..124

    const float* Ap = A + (size_t)(row0 + ar) * K + ak;
    const float* Bp = B + (size_t)br * N + col0 + bc;

    float acc[8][8];
    #pragma unroll
    for (int i = 0; i < 8; i++)
        #pragma unroll
        for (int j = 0; j < 8; j++) acc[i][j] = 0.f;

    for (int k0 = 0; k0 < K; k0 += 8) {
        float4 av = *(const float4*)(Ap + k0);
        float4 bv = *(const float4*)(Bp + (size_t)k0 * N);
        __syncthreads();
        As[ak + 0][ar] = av.x;
        As[ak + 1][ar] = av.y;
        As[ak + 2][ar] = av.z;
        As[ak + 3][ar] = av.w;
        *(float4*)&Bs[br][bc] = bv;
        __syncthreads();

        #pragma unroll
        for (int k = 0; k < 8; k++) {
            float4 a0 = *(const float4*)&As[k][ty * 8];
            float4 a1 = *(const float4*)&As[k][ty * 8 + 4];
            float4 b0 = *(const float4*)&Bs[k][tx * 8];
            float4 b1 = *(const float4*)&Bs[k][tx * 8 + 4];
            float a[8] = {a0.x,a0.y,a0.z,a0.w,a1.x,a1.y,a1.z,a1.w};
            float b[8] = {b0.x,b0.y,b0.z,b0.w,b1.x,b1.y,b1.z,b1.w};
            #pragma unroll
            for (int i = 0; i < 8; i++)
                #pragma unroll
                for (int j = 0; j < 8; j++)
                    acc[i][j] += a[i] * b[j];
        }
    }

    #pragma unroll
    for (int i = 0; i < 8; i++) {
        int row = row0 + ty * 8 + i;
        #pragma unroll
        for (int j = 0; j < 8; j++) {
            int col = col0 + tx * 8 + j;
            float c = acc[i][j] + bias[col];
            if (head_split) {
                int b = row >> 11, s = row & 2047;
                int h = col >> 6,  d = col & 63;
                C[((((size_t)b * NH + h) * SS + s) * HD) + d] = c;
            } else {
                C[(size_t)row * N + col] = c;
            }
        }
    }
}

// ---------------------------------------------------------------------------
// Flash attention (causal). One block = one (b,h) x 64-query tile.
// 256 threads (8 warps). Warp w owns rows w*8..w*8+7.
// KV tiles of 32 keys. Online softmax.
// ---------------------------------------------------------------------------
__global__ __launch_bounds__(256) void attn_kernel(
    const float* __restrict__ Q, const float* __restrict__ K,
    const float* __restrict__ V, float* __restrict__ O)
{
    __shared__ float Qt[64][64];   // Qt[d][r]
    __shared__ float Kt[64][32];   // Kt[d][c]
    __shared__ float Vs[32][64];   // Vs[c][d]
    __shared__ float Ps[64][32];   // Ps[r][c]

    const int bh   = blockIdx.y;           // 0..31
    const int q0   = blockIdx.x * 64;
    const int tid  = threadIdx.x;
    const int warp = tid >> 5;
    const int lane = tid & 31;
    const int r0   = warp * 8;

    const float* Qb = Q + (size_t)bh * SS * HD;
    const float* Kb = K + (size_t)bh * SS * HD;
    const float* Vb = V + (size_t)bh * SS * HD;

    // load Q tile transposed
    {
        int r  = tid >> 4;
        int d4 = (tid & 15) * 4;
        #pragma unroll
        for (int it = 0; it < 4; it++) {
            int rr = r + it * 16;
            float4 v = *(const float4*)(Qb + (size_t)(q0 + rr) * HD + d4);
            Qt[d4 + 0][rr] = v.x;
            Qt[d4 + 1][rr] = v.y;
            Qt[d4 + 2][rr] = v.z;
            Qt[d4 + 3][rr] = v.w;
        }
    }

    float o[8][2], m[8], l[8];
    #pragma unroll
    for (int i = 0; i < 8; i++) {
        o[i][0] = 0.f; o[i][1] = 0.f;
        m[i] = -INFINITY; l[i] = 0.f;
    }

    const float sc = 0.125f;                 // 1/sqrt(64)
    const int nk = (q0 + 64) / 32;           // kv tiles covering keys <= q0+63
    const int d0 = lane * 2;

    for (int kt = 0; kt < nk; kt++) {
        const int k0 = kt * 32;
        __syncthreads();   // previous tile fully consumed
        {
            int c  = tid >> 4;
            int d4 = (tid & 15) * 4;
            #pragma unroll
            for (int it = 0; it < 2; it++) {
                int cc = c + it * 16;
                float4 kv = *(const float4*)(Kb + (size_t)(k0 + cc) * HD + d4);
                Kt[d4 + 0][cc] = kv.x;
                Kt[d4 + 1][cc] = kv.y;
                Kt[d4 + 2][cc] = kv.z;
                Kt[d4 + 3][cc] = kv.w;
                float4 vv = *(const float4*)(Vb + (size_t)(k0 + cc) * HD + d4);
                *(float4*)&Vs[cc][d4] = vv;
            }
        }
        __syncthreads();

        // skip tiles fully masked for this warp's rows
        if (k0 > q0 + r0 + 7) continue;

        // S = Q K^T : lane owns column 'lane'
        float s[8];
        #pragma unroll
        for (int i = 0; i < 8; i++) s[i] = 0.f;
        #pragma unroll
        for (int d = 0; d < 64; d++) {
            float kv = Kt[d][lane];
            float4 qa = *(const float4*)&Qt[d][r0];
            float4 qb = *(const float4*)&Qt[d][r0 + 4];
            s[0] += qa.x * kv; s[1] += qa.y * kv;
            s[2] += qa.z * kv; s[3] += qa.w * kv;
            s[4] += qb.x * kv; s[5] += qb.y * kv;
            s[6] += qb.z * kv; s[7] += qb.w * kv;
        }

        // mask + scale
        #pragma unroll
        for (int i = 0; i < 8; i++) {
            int qg = q0 + r0 + i;
            int kg = k0 + lane;
            s[i] = (kg <= qg) ? s[i] * sc : -INFINITY;
        }

        // online softmax per row
        #pragma unroll
        for (int i = 0; i < 8; i++) {
            float mx = s[i];
            #pragma unroll
            for (int off = 16; off > 0; off >>= 1)
                mx = fmaxf(mx, __shfl_xor_sync(0xFFFFFFFFu, mx, off));
            float mnew  = fmaxf(m[i], mx);
            float alpha = __expf(m[i] - mnew);
            float p     = __expf(s[i] - mnew);
            float ps = p;
            #pragma unroll
            for (int off = 16; off > 0; off >>= 1)
                ps += __shfl_xor_sync(0xFFFFFFFFu, ps, off);
            l[i] = l[i] * alpha + ps;
            m[i] = mnew;
            o[i][0] *= alpha;
            o[i][1] *= alpha;
            Ps[r0 + i][lane] = p;
        }
        __syncwarp();

        // O += P @ V : lane owns dims d0, d0+1
        #pragma unroll
        for (int c = 0; c < 32; c++) {
            float2 v = *(const float2*)&Vs[c][d0];
            #pragma unroll
            for (int i = 0; i < 8; i++) {
                float p = Ps[r0 + i][c];
                o[i][0] += p * v.x;
                o[i][1] += p * v.y;
            }
        }
    }

    // write O in [b, s, h*64+d] layout
    const int b = bh >> 4, h = bh & 15;
    #pragma unroll
    for (int i = 0; i < 8; i++) {
        float inv = 1.f / l[i];
        int sg = q0 + r0 + i;
        float* dst = O + ((size_t)(b * SS + sg)) * DM + h * HD + d0;
        float2 w;
        w.x = o[i][0] * inv;
        w.y = o[i][1] * inv;
        *(float2*)dst = w;
    }
}

// ---------------------------------------------------------------------------
extern "C" void kernel_launch(void* const* d_in, const int* in_sizes, int n_in,
                              void* d_out, int out_size)
{
    const float* x  = (const float*)d_in[0];
    const float* Wq = (const float*)d_in[1];
    const float* bq = (const float*)d_in[2];
    const float* Wk = (const float*)d_in[3];
    const float* bk = (const float*)d_in[4];
    const float* Wv = (const float*)d_in[5];
    const float* bv = (const float*)d_in[6];
    const float* Wo = (const float*)d_in[7];
    const float* bo = (const float*)d_in[8];

    float *qp, *kp, *vp, *ap;
    cudaGetSymbolAddress((void**)&qp, g_Q);
    cudaGetSymbolAddress((void**)&kp, g_K);
    cudaGetSymbolAddress((void**)&vp, g_V);
    cudaGetSymbolAddress((void**)&ap, g_att);

    dim3 gg(DM / 128, MROWS / 128);   // (8, 32)
    gemm128<<<gg, 256>>>(x, Wq, bq, qp, MROWS, DM, DM, 1);
    gemm128<<<gg, 256>>>(x, Wk, bk, kp, MROWS, DM, DM, 1);
    gemm128<<<gg, 256>>>(x, Wv, bv, vp, MROWS, DM, DM, 1);

    attn_kernel<<<dim3(SS / 64, BB * NH), 256>>>(qp, kp, vp, ap);

    gemm128<<<gg, 256>>>(ap, Wo, bo, (float*)d_out, MROWS, DM, DM, 0);
}

// round 2
// speedup vs baseline: 1.0097x; 1.0097x over previous
#include <cuda_runtime.h>
#include <math.h>

// Problem constants
#define BB 2
#define SS 2048
#define DM 1024
#define NH 16
#define HD 64
#define MROWS (BB*SS)        // 4096

// Scratch (device globals; no allocations allowed)
__device__ float g_Q[BB*NH*SS*HD];     // [b,h,s,d]
__device__ float g_K[BB*NH*SS*HD];
__device__ float g_V[BB*NH*SS*HD];
__device__ float g_att[BB*SS*DM];      // [b,s, h*64+d]

// ---------------------------------------------------------------------------
// Tiled SGEMM: C[M,N] = A[M,K] @ B[K,N] + bias[N]
// BM=BN=128, BK=8, 256 threads, 8x8 per thread.
// head_split: write C in [b,h,s,d] layout instead of row-major.
// ---------------------------------------------------------------------------
__global__ __launch_bounds__(256) void gemm128(
    const float* __restrict__ A, const float* __restrict__ B,
    const float* __restrict__ bias, float* __restrict__ C,
    int M, int N, int K, int head_split)
{
    __shared__ float As[8][128];   // As[k][m]
    __shared__ float Bs[8][128];   // Bs[k][n]

    const int tid  = threadIdx.x;
    const int row0 = blockIdx.y * 128;
    const int col0 = blockIdx.x * 128;
    const int ty   = tid >> 4;     // 0..15
    const int tx   = tid & 15;     // 0..15

    // global load mapping
    const int ar = tid >> 1;           // 0..127
    const int ak = (tid & 1) * 4;      // 0 or 4
    const int br = tid >> 5;           // 0..7
    const int bc = (tid & 31) * 4;     // 0..124

    const float* Ap = A + (size_t)(row0 + ar) * K + ak;
    const float* Bp = B + (size_t)br * N + col0 + bc;

    float acc[8][8];
    #pragma unroll
    for (int i = 0; i < 8; i++)
        #pragma unroll
        for (int j = 0; j < 8; j++) acc[i][j] = 0.f;

    for (int k0 = 0; k0 < K; k0 += 8) {
        float4 av = *(const float4*)(Ap + k0);
        float4 bv = *(const float4*)(Bp + (size_t)k0 * N);
        __syncthreads();
        As[ak + 0][ar] = av.x;
        As[ak + 1][ar] = av.y;
        As[ak + 2][ar] = av.z;
        As[ak + 3][ar] = av.w;
        *(float4*)&Bs[br][bc] = bv;
        __syncthreads();

        #pragma unroll
        for (int k = 0; k < 8; k++) {
            float4 a0 = *(const float4*)&As[k][ty * 8];
            float4 a1 = *(const float4*)&As[k][ty * 8 + 4];
            float4 b0 = *(const float4*)&Bs[k][tx * 8];
            float4 b1 = *(const float4*)&Bs[k][tx * 8 + 4];
            float a[8] = {a0.x,a0.y,a0.z,a0.w,a1.x,a1.y,a1.z,a1.w};
            float b[8] = {b0.x,b0.y,b0.z,b0.w,b1.x,b1.y,b1.z,b1.w};
            #pragma unroll
            for (int i = 0; i < 8; i++)
                #pragma unroll
                for (int j = 0; j < 8; j++)
                    acc[i][j] += a[i] * b[j];
        }
    }

    #pragma unroll
    for (int i = 0; i < 8; i++) {
        int row = row0 + ty * 8 + i;
        #pragma unroll
        for (int j = 0; j < 8; j++) {
            int col = col0 + tx * 8 + j;
            float c = acc[i][j] + bias[col];
            if (head_split) {
                int b = row >> 11, s = row & 2047;
                int h = col >> 6,  d = col & 63;
                C[((((size_t)b * NH + h) * SS + s) * HD) + d] = c;
            } else {
                C[(size_t)row * N + col] = c;
            }
        }
    }
}

// ---------------------------------------------------------------------------
// Flash attention (causal). One block = one (b,h) x 64-query tile.
// 256 threads (8 warps). Warp w owns rows w*8..w*8+7.
// KV tiles of 32 keys. Online softmax.
// ---------------------------------------------------------------------------
__global__ __launch_bounds__(256) void attn_kernel(
    const float* __restrict__ Q, const float* __restrict__ K,
    const float* __restrict__ V, float* __restrict__ O)
{
    __shared__ float Qt[64][64];   // Qt[d][r]
    __shared__ float Kt[64][32];   // Kt[d][c]
    __shared__ float Vs[32][64];   // Vs[c][d]
    __shared__ float Ps[64][32];   // Ps[r][c]

    const int bh   = blockIdx.y;           // 0..31
    const int q0   = blockIdx.x * 64;
    const int tid  = threadIdx.x;
    const int warp = tid >> 5;
    const int lane = tid & 31;
    const int r0   = warp * 8;

    const float* Qb = Q + (size_t)bh * SS * HD;
    const float* Kb = K + (size_t)bh * SS * HD;
    const float* Vb = V + (size_t)bh * SS * HD;

    // load Q tile transposed
    {
        int r  = tid >> 4;
        int d4 = (tid & 15) * 4;
        #pragma unroll
        for (int it = 0; it < 4; it++) {
            int rr = r + it * 16;
            float4 v = *(const float4*)(Qb + (size_t)(q0 + rr) * HD + d4);
            Qt[d4 + 0][rr] = v.x;
            Qt[d4 + 1][rr] = v.y;
            Qt[d4 + 2][rr] = v.z;
            Qt[d4 + 3][rr] = v.w;
        }
    }

    float o[8][2], m[8], l[8];
    #pragma unroll
    for (int i = 0; i < 8; i++) {
        o[i][0] = 0.f; o[i][1] = 0.f;
        m[i] = -INFINITY; l[i] = 0.f;
    }

    const float sc = 0.125f;                 // 1/sqrt(64)
    const int nk = (q0 + 64) / 32;           // kv tiles covering keys <= q0+63
    const int d0 = lane * 2;

    for (int kt = 0; kt < nk; kt++) {
        const int k0 = kt * 32;
        __syncthreads();   // previous tile fully consumed
        {
            int c  = tid >> 4;
            int d4 = (tid & 15) * 4;
            #pragma unroll
            for (int it = 0; it < 2; it++) {
                int cc = c + it * 16;
                float4 kv = *(const float4*)(Kb + (size_t)(k0 + cc) * HD + d4);
                Kt[d4 + 0][cc] = kv.x;
                Kt[d4 + 1][cc] = kv.y;
                Kt[d4 + 2][cc] = kv.z;
                Kt[d4 + 3][cc] = kv.w;
                float4 vv = *(const float4*)(Vb + (size_t)(k0 + cc) * HD + d4);
                *(float4*)&Vs[cc][d4] = vv;
            }
        }
        __syncthreads();

        // skip tiles fully masked for this warp's rows
        if (k0 > q0 + r0 + 7) continue;

        // S = Q K^T : lane owns column 'lane'
        float s[8];
        #pragma unroll
        for (int i = 0; i < 8; i++) s[i] = 0.f;
        #pragma unroll
        for (int d = 0; d < 64; d++) {
            float kv = Kt[d][lane];
            float4 qa = *(const float4*)&Qt[d][r0];
            float4 qb = *(const float4*)&Qt[d][r0 + 4];
            s[0] += qa.x * kv; s[1] += qa.y * kv;
            s[2] += qa.z * kv; s[3] += qa.w * kv;
            s[4] += qb.x * kv; s[5] += qb.y * kv;
            s[6] += qb.z * kv; s[7] += qb.w * kv;
        }

        // mask + scale
        #pragma unroll
        for (int i = 0; i < 8; i++) {
            int qg = q0 + r0 + i;
            int kg = k0 + lane;
            s[i] = (kg <= qg) ? s[i] * sc : -INFINITY;
        }

        // online softmax per row
        #pragma unroll
        for (int i = 0; i < 8; i++) {
            float mx = s[i];
            #pragma unroll
            for (int off = 16; off > 0; off >>= 1)
                mx = fmaxf(mx, __shfl_xor_sync(0xFFFFFFFFu, mx, off));
            float mnew  = fmaxf(m[i], mx);
            float alpha = __expf(m[i] - mnew);
            float p     = __expf(s[i] - mnew);
            float ps = p;
            #pragma unroll
            for (int off = 16; off > 0; off >>= 1)
                ps += __shfl_xor_sync(0xFFFFFFFFu, ps, off);
            l[i] = l[i] * alpha + ps;
            m[i] = mnew;
            o[i][0] *= alpha;
            o[i][1] *= alpha;
            Ps[r0 + i][lane] = p;
        }
        __syncwarp();

        // O += P @ V : lane owns dims d0, d0+1
        #pragma unroll
        for (int c = 0; c < 32; c++) {
            float2 v = *(const float2*)&Vs[c][d0];
            #pragma unroll
            for (int i = 0; i < 8; i++) {
                float p = Ps[r0 + i][c];
                o[i][0] += p * v.x;
                o[i][1] += p * v.y;
            }
        }
    }

    // write O in [b, s, h*64+d] layout
    const int b = bh >> 4, h = bh & 15;
    #pragma unroll
    for (int i = 0; i < 8; i++) {
        float inv = 1.f / l[i];
        int sg = q0 + r0 + i;
        float* dst = O + ((size_t)(b * SS + sg)) * DM + h * HD + d0;
        float2 w;
        w.x = o[i][0] * inv;
        w.y = o[i][1] * inv;
        *(float2*)dst = w;
    }
}

// ---------------------------------------------------------------------------
extern "C" void kernel_launch(void* const* d_in, const int* in_sizes, int n_in,
                              void* d_out, int out_size)
{
    const float* x  = (const float*)d_in[0];
    const float* Wq = (const float*)d_in[1];
    const float* bq = (const float*)d_in[2];
    const float* Wk = (const float*)d_in[3];
    const float* bk = (const float*)d_in[4];
    const float* Wv = (const float*)d_in[5];
    const float* bv = (const float*)d_in[6];
    const float* Wo = (const float*)d_in[7];
    const float* bo = (const float*)d_in[8];

    float *qp, *kp, *vp, *ap;
    cudaGetSymbolAddress((void**)&qp, g_Q);
    cudaGetSymbolAddress((void**)&kp, g_K);
    cudaGetSymbolAddress((void**)&vp, g_V);
    cudaGetSymbolAddress((void**)&ap, g_att);

    dim3 gg(DM / 128, MROWS / 128);   // (8, 32)
    gemm128<<<gg, 256>>>(x, Wq, bq, qp, MROWS, DM, DM, 1);
    gemm128<<<gg, 256>>>(x, Wk, bk, kp, MROWS, DM, DM, 1);
    gemm128<<<gg, 256>>>(x, Wv, bv, vp, MROWS, DM, DM, 1);

    attn_kernel<<<dim3(SS / 64, BB * NH), 256>>>(qp, kp, vp, ap);

    gemm128<<<gg, 256>>>(ap, Wo, bo, (float*)d_out, MROWS, DM, DM, 0);
}